// round 8
// baseline (speedup 1.0000x reference)
#include <cuda_runtime.h>
#include <cstdint>

#define N_NODES 100000
#define IN_CH 128
#define HID 32
#define MAX_E 3400000
#define SCAN_B 1024
#define MAX_PART 128

// ---- scratch: device globals. Referenced ONLY from device code. ----
__device__ __align__(16) float g_h[N_NODES * HID];    // hs1 = (x@W1)*dinv
__device__ __align__(16) float g_acc[N_NODES * HID];  // hs2 = (relu(l1)@W2)*dinv
__device__ int   g_deg[N_NODES];
__device__ float g_dinv[N_NODES];
__device__ int   g_off[N_NODES + 1];
__device__ int   g_cursor[N_NODES];
__device__ int   g_csr_src[MAX_E];
__device__ int   g_bsum[MAX_PART];
__device__ int   g_bflag[MAX_PART];
__device__ int   g_is64;

// ---- packed f32x2 helpers (Blackwell FFMA2) ----
__device__ __forceinline__ unsigned long long pack2(float a, float b) {
    unsigned long long r;
    asm("mov.b64 %0, {%1, %2};" : "=l"(r) : "f"(a), "f"(b));
    return r;
}
__device__ __forceinline__ unsigned long long fma2(unsigned long long a,
                                                   unsigned long long b,
                                                   unsigned long long c) {
    unsigned long long d;
    asm("fma.rn.f32x2 %0, %1, %2, %3;" : "=l"(d) : "l"(a), "l"(b), "l"(c));
    return d;
}
__device__ __forceinline__ float2 unpack2(unsigned long long v) {
    float2 f;
    asm("mov.b64 {%0, %1}, %2;" : "=f"(f.x), "=f"(f.y) : "l"(v));
    return f;
}

// ---------------- dtype probe + zero deg + zero scan flags (fused) ----------------
__global__ void k_detect_zero(const int* __restrict__ ei32, int E, int n) {
    int i = blockIdx.x * blockDim.x + threadIdx.x;
    if (i < n) g_deg[i] = 0;
    if (i < MAX_PART) { g_bflag[i] = 0; g_bsum[i] = 0; }
    if (blockIdx.x == 0) {
        __shared__ int nz;
        if (threadIdx.x == 0) nz = 0;
        __syncthreads();
        int m = (E > 256) ? 256 : E;
        if (threadIdx.x < m) {
            if (ei32[2 * threadIdx.x + 1] != 0) nz = 1;  // benign race
        }
        __syncthreads();
        if (threadIdx.x == 0) g_is64 = (nz == 0);
    }
}

__global__ void k_deg(const int* __restrict__ ei32, int E) {
    int e = blockIdx.x * blockDim.x + threadIdx.x;
    if (e >= E) return;
    int d = g_is64 ? (int)((const long long*)ei32)[E + e] : ei32[E + e];
    atomicAdd(&g_deg[d], 1);
}

// ---------------- single-kernel scan (decoupled chained prefix, int-exact) --------
__global__ void k_scan(int n, int E) {
    __shared__ int s[SCAN_B];
    __shared__ int sprev;
    int t = threadIdx.x, b = blockIdx.x;
    int i = b * SCAN_B + t;
    int deg = (i < n) ? g_deg[i] : 0;
    s[t] = deg;
    __syncthreads();
    for (int d = 1; d < SCAN_B; d <<= 1) {
        int v = (t >= d) ? s[t - d] : 0;
        __syncthreads();
        s[t] += v;
        __syncthreads();
    }
    if (t == SCAN_B - 1) {
        int total = s[t];
        int prev = 0;
        if (b > 0) {
            while (atomicAdd(&g_bflag[b - 1], 0) == 0) { }
            __threadfence();
            prev = g_bsum[b - 1];
        }
        g_bsum[b] = prev + total;
        __threadfence();
        atomicExch(&g_bflag[b], 1);
        sprev = prev;
    }
    __syncthreads();
    if (i < n) {
        int excl = s[t] - deg + sprev;
        g_off[i] = excl;
        g_cursor[i] = excl;
        g_dinv[i] = rsqrtf((float)deg + 1.0f);  // +1 self-loop
    }
    if (b == gridDim.x - 1 && t == SCAN_B - 1) g_off[n] = E;
}

__global__ void k_fill(const int* __restrict__ ei32, int E) {
    int e = blockIdx.x * blockDim.x + threadIdx.x;
    if (e >= E) return;
    int s, d;
    if (g_is64) {
        s = (int)((const long long*)ei32)[e];
        d = (int)((const long long*)ei32)[E + e];
    } else {
        s = ei32[e];
        d = ei32[E + e];
    }
    int pos = atomicAdd(&g_cursor[d], 1);
    g_csr_src[pos] = s;
}

// ---------------- GEMM1: hs1 = (x@W1)*di (packed f32x2 FMA) ----------------
__global__ void k_gemm1(const float* __restrict__ x,
                        const float* __restrict__ W1, int n) {
    __shared__ __align__(16) float4 sW4[IN_CH * 8];   // 16 KB
    __shared__ __align__(16) float4 sx4[32 * 32];     // 16 KB
    int tid = threadIdx.x;
    int nodeBase = blockIdx.x * 32;

    for (int i = tid; i < IN_CH * 8; i += 256) sW4[i] = ((const float4*)W1)[i];
    for (int i = tid; i < 32 * 32; i += 256) {
        int nd = i >> 5, q = i & 31;
        int node = nodeBase + nd;
        sx4[i] = (node < n) ? ((const float4*)x)[(size_t)node * 32 + q]
                            : make_float4(0.f, 0.f, 0.f, 0.f);
    }
    __syncthreads();

    int nd = tid >> 3;
    int q = tid & 7;
    int node = nodeBase + nd;
    if (node >= n) return;

    const ulonglong2* sWu = (const ulonglong2*)sW4;
    unsigned long long a01 = 0ULL, a23 = 0ULL;
#pragma unroll 8
    for (int k4 = 0; k4 < 32; k4++) {
        float4 xv = sx4[nd * 32 + k4];
        unsigned long long d0 = pack2(xv.x, xv.x);
        unsigned long long d1 = pack2(xv.y, xv.y);
        unsigned long long d2 = pack2(xv.z, xv.z);
        unsigned long long d3 = pack2(xv.w, xv.w);
        ulonglong2 w0 = sWu[(4 * k4 + 0) * 8 + q];
        ulonglong2 w1 = sWu[(4 * k4 + 1) * 8 + q];
        ulonglong2 w2 = sWu[(4 * k4 + 2) * 8 + q];
        ulonglong2 w3 = sWu[(4 * k4 + 3) * 8 + q];
        a01 = fma2(d0, w0.x, a01); a23 = fma2(d0, w0.y, a23);
        a01 = fma2(d1, w1.x, a01); a23 = fma2(d1, w1.y, a23);
        a01 = fma2(d2, w2.x, a01); a23 = fma2(d2, w2.y, a23);
        a01 = fma2(d3, w3.x, a01); a23 = fma2(d3, w3.y, a23);
    }
    float2 lo = unpack2(a01), hi = unpack2(a23);
    float di = g_dinv[node];
    float4 hs = make_float4(lo.x * di, lo.y * di, hi.x * di, hi.y * di);
    ((float4*)g_h)[(size_t)node * 8 + q] = hs;
}

// ---------------- agg1 fused with GEMM2 ----------------
// per warp/node: r = relu(b1 + dd*(sum_in hs1 + hs1_self));  hs2 = (r @ W2)*dd -> g_acc
__global__ void k_agg1_gemm2(const float* __restrict__ b1,
                             const float* __restrict__ W2, int n) {
    __shared__ __align__(16) float sW[HID * HID];     // 4 KB: W2[k][c]
    int tid = threadIdx.x;
    for (int i = tid; i < HID * HID; i += 256) sW[i] = W2[i];
    __syncthreads();

    int warp_id = (blockIdx.x * blockDim.x + tid) >> 5;
    if (warp_id >= n) return;
    int node = warp_id;
    int lane = tid & 31;
    int j = lane >> 3;  // edge slot
    int q = lane & 7;   // float4 quad

    int beg = g_off[node];
    int end = g_off[node + 1];

    const float4* H = (const float4*)g_h;
    float4 acc = make_float4(0.f, 0.f, 0.f, 0.f);
#pragma unroll 4
    for (int i = beg + j; i < end; i += 4) {
        int s = g_csr_src[i];
        float4 v = __ldg(&H[(size_t)s * 8 + q]);
        acc.x += v.x; acc.y += v.y; acc.z += v.z; acc.w += v.w;
    }
#pragma unroll
    for (int m = 8; m <= 16; m <<= 1) {
        acc.x += __shfl_xor_sync(0xFFFFFFFFu, acc.x, m);
        acc.y += __shfl_xor_sync(0xFFFFFFFFu, acc.y, m);
        acc.z += __shfl_xor_sync(0xFFFFFFFFu, acc.z, m);
        acc.w += __shfl_xor_sync(0xFFFFFFFFu, acc.w, m);
    }
    // every lane now holds the full sum for quad q = lane&7
    float dd = g_dinv[node];
    float4 self = __ldg(&H[(size_t)node * 8 + q]);
    float4 bv = __ldg(((const float4*)b1) + q);
    float4 r;
    r.x = fmaxf(fmaf(dd, acc.x + self.x, bv.x), 0.f);
    r.y = fmaxf(fmaf(dd, acc.y + self.y, bv.y), 0.f);
    r.z = fmaxf(fmaf(dd, acc.z + self.z, bv.z), 0.f);
    r.w = fmaxf(fmaf(dd, acc.w + self.w, bv.w), 0.f);

    // GEMM2 in-warp: lane c computes h2[c] = sum_k r[k] * W2[k][c]
    int c = lane;
    float h2 = 0.f;
#pragma unroll
    for (int k4 = 0; k4 < 8; k4++) {
        float vx = __shfl_sync(0xFFFFFFFFu, r.x, k4);
        float vy = __shfl_sync(0xFFFFFFFFu, r.y, k4);
        float vz = __shfl_sync(0xFFFFFFFFu, r.z, k4);
        float vw = __shfl_sync(0xFFFFFFFFu, r.w, k4);
        h2 = fmaf(vx, sW[(4 * k4 + 0) * HID + c], h2);
        h2 = fmaf(vy, sW[(4 * k4 + 1) * HID + c], h2);
        h2 = fmaf(vz, sW[(4 * k4 + 2) * HID + c], h2);
        h2 = fmaf(vw, sW[(4 * k4 + 3) * HID + c], h2);
    }
    g_acc[(size_t)node * HID + c] = h2 * dd;   // hs2, coalesced 128B store
}

// ---------------- agg2: out = b2 + dd*(sum_in hs2 + hs2_self) --------------------
__global__ void k_aggregate2(const float* __restrict__ b2,
                             float* __restrict__ out, int n) {
    int warp_id = (blockIdx.x * blockDim.x + threadIdx.x) >> 5;
    if (warp_id >= n) return;
    int node = warp_id;
    int lane = threadIdx.x & 31;
    int j = lane >> 3;
    int q = lane & 7;

    int beg = g_off[node];
    int end = g_off[node + 1];

    const float4* H = (const float4*)g_acc;
    float4 acc = make_float4(0.f, 0.f, 0.f, 0.f);
#pragma unroll 4
    for (int i = beg + j; i < end; i += 4) {
        int s = g_csr_src[i];
        float4 v = __ldg(&H[(size_t)s * 8 + q]);
        acc.x += v.x; acc.y += v.y; acc.z += v.z; acc.w += v.w;
    }
#pragma unroll
    for (int m = 8; m <= 16; m <<= 1) {
        acc.x += __shfl_xor_sync(0xFFFFFFFFu, acc.x, m);
        acc.y += __shfl_xor_sync(0xFFFFFFFFu, acc.y, m);
        acc.z += __shfl_xor_sync(0xFFFFFFFFu, acc.z, m);
        acc.w += __shfl_xor_sync(0xFFFFFFFFu, acc.w, m);
    }
    if (j == 0) {
        float dd = g_dinv[node];
        float4 self = __ldg(&H[(size_t)node * 8 + q]);
        float4 bv = __ldg(((const float4*)b2) + q);
        float4 r;
        r.x = fmaf(dd, acc.x + self.x, bv.x);
        r.y = fmaf(dd, acc.y + self.y, bv.y);
        r.z = fmaf(dd, acc.z + self.z, bv.z);
        r.w = fmaf(dd, acc.w + self.w, bv.w);
        ((float4*)(out + (size_t)node * HID))[q] = r;
    }
}

extern "C" void kernel_launch(void* const* d_in, const int* in_sizes, int n_in,
                              void* d_out, int out_size) {
    const float* x  = (const float*)d_in[0];
    const int*   ei = (const int*)d_in[1];
    const float* W1 = (const float*)d_in[2];
    const float* b1 = (const float*)d_in[3];
    const float* W2 = (const float*)d_in[4];
    const float* b2 = (const float*)d_in[5];
    float* out = (float*)d_out;

    const int N = in_sizes[0] / IN_CH;
    const int E = in_sizes[1] / 2;
    const int nb = (N + SCAN_B - 1) / SCAN_B;

    k_detect_zero<<<(N + 255) / 256, 256>>>(ei, E, N);   // 1
    k_deg<<<(E + 255) / 256, 256>>>(ei, E);              // 2
    k_scan<<<nb, SCAN_B>>>(N, E);                        // 3
    k_fill<<<(E + 255) / 256, 256>>>(ei, E);             // 4
    k_gemm1<<<(N + 31) / 32, 256>>>(x, W1, N);           // 5
    {
        long long thr = (long long)N * 32;
        k_agg1_gemm2<<<(int)((thr + 255) / 256), 256>>>(b1, W2, N);   // 6
        k_aggregate2<<<(int)((thr + 255) / 256), 256>>>(b2, out, N);  // 7
    }
}

// round 9
// speedup vs baseline: 1.6145x; 1.6145x over previous
#include <cuda_runtime.h>
#include <cstdint>

#define N_NODES 100000
#define IN_CH 128
#define HID 32
#define MAX_E 3400000
#define SCAN_B 1024
#define MAX_PART 128

// ---- scratch: device globals. Referenced ONLY from device code. ----
__device__ __align__(16) float g_h[N_NODES * HID];    // hs = (x@W)*dinv per layer
__device__ __align__(16) float g_acc[N_NODES * HID];  // layer-1 aggregated output
__device__ int   g_deg[N_NODES];
__device__ float g_dinv[N_NODES];
__device__ int   g_off[N_NODES + 1];
__device__ int   g_csr_src[MAX_E];
__device__ int   g_pos[MAX_E];        // edge rank within its dst bucket
__device__ int   g_part[MAX_PART];
__device__ int   g_partoff[MAX_PART];
__device__ int   g_is64;

// ---- packed f32x2 helpers (Blackwell FFMA2) ----
__device__ __forceinline__ unsigned long long pack2(float a, float b) {
    unsigned long long r;
    asm("mov.b64 %0, {%1, %2};" : "=l"(r) : "f"(a), "f"(b));
    return r;
}
__device__ __forceinline__ unsigned long long fma2(unsigned long long a,
                                                   unsigned long long b,
                                                   unsigned long long c) {
    unsigned long long d;
    asm("fma.rn.f32x2 %0, %1, %2, %3;" : "=l"(d) : "l"(a), "l"(b), "l"(c));
    return d;
}
__device__ __forceinline__ float2 unpack2(unsigned long long v) {
    float2 f;
    asm("mov.b64 {%0, %1}, %2;" : "=f"(f.x), "=f"(f.y) : "l"(v));
    return f;
}

// ---------------- dtype probe + zero deg (fused) ----------------
__global__ void k_detect_zero(const int* __restrict__ ei32, int E, int n) {
    int i = blockIdx.x * blockDim.x + threadIdx.x;
    if (i < n) g_deg[i] = 0;
    if (blockIdx.x == 0) {
        __shared__ int nz;
        if (threadIdx.x == 0) nz = 0;
        __syncthreads();
        int m = (E > 256) ? 256 : E;
        if (threadIdx.x < m) {
            if (ei32[2 * threadIdx.x + 1] != 0) nz = 1;  // benign race
        }
        __syncthreads();
        if (threadIdx.x == 0) g_is64 = (nz == 0);
    }
}

// ---------------- degree + per-edge bucket rank ----------------
__global__ void k_deg(const int* __restrict__ ei32, int E) {
    int e = blockIdx.x * blockDim.x + threadIdx.x;
    if (e >= E) return;
    int d = g_is64 ? (int)((const long long*)ei32)[E + e] : ei32[E + e];
    g_pos[e] = atomicAdd(&g_deg[d], 1);
}

// ---------------- scan (3-kernel, proven) ----------------
__global__ void k_partial(int n) {
    __shared__ int s[SCAN_B];
    int t = threadIdx.x;
    int i = blockIdx.x * SCAN_B + t;
    s[t] = (i < n) ? g_deg[i] : 0;
    __syncthreads();
    for (int d = SCAN_B / 2; d > 0; d >>= 1) {
        if (t < d) s[t] += s[t + d];
        __syncthreads();
    }
    if (t == 0) g_part[blockIdx.x] = s[0];
}

__global__ void k_scanpart(int nb, int n, int E) {
    __shared__ int s[MAX_PART];
    int t = threadIdx.x;
    s[t] = (t < nb) ? g_part[t] : 0;
    __syncthreads();
    for (int d = 1; d < MAX_PART; d <<= 1) {
        int v = (t >= d) ? s[t - d] : 0;
        __syncthreads();
        s[t] += v;
        __syncthreads();
    }
    if (t < nb) g_partoff[t] = (t == 0) ? 0 : s[t - 1];
    if (t == 0) g_off[n] = E;
}

__global__ void k_local(int n) {
    __shared__ int s[SCAN_B];
    int t = threadIdx.x;
    int i = blockIdx.x * SCAN_B + t;
    int deg = (i < n) ? g_deg[i] : 0;
    s[t] = deg;
    __syncthreads();
    for (int d = 1; d < SCAN_B; d <<= 1) {
        int v = (t >= d) ? s[t - d] : 0;
        __syncthreads();
        s[t] += v;
        __syncthreads();
    }
    if (i < n) {
        int excl = s[t] - deg + g_partoff[blockIdx.x];
        g_off[i] = excl;
        g_dinv[i] = rsqrtf((float)deg + 1.0f);  // +1 self-loop
    }
}

// ---------------- CSR fill: NO atomics (rank precomputed) ----------------
__global__ void k_fill(const int* __restrict__ ei32, int E) {
    int e = blockIdx.x * blockDim.x + threadIdx.x;
    if (e >= E) return;
    int s, d;
    if (g_is64) {
        s = (int)((const long long*)ei32)[e];
        d = (int)((const long long*)ei32)[E + e];
    } else {
        s = ei32[e];
        d = ei32[E + e];
    }
    g_csr_src[g_off[d] + g_pos[e]] = s;
}

// ---------------- GEMM1: hs = (x@W1)*di (packed f32x2 FMA) ----------------
__global__ void k_gemm1(const float* __restrict__ x,
                        const float* __restrict__ W1, int n) {
    __shared__ __align__(16) float4 sW4[IN_CH * 8];   // 16 KB
    __shared__ __align__(16) float4 sx4[32 * 32];     // 16 KB
    int tid = threadIdx.x;
    int nodeBase = blockIdx.x * 32;

    for (int i = tid; i < IN_CH * 8; i += 256) sW4[i] = ((const float4*)W1)[i];
    for (int i = tid; i < 32 * 32; i += 256) {
        int nd = i >> 5, q = i & 31;
        int node = nodeBase + nd;
        sx4[i] = (node < n) ? ((const float4*)x)[(size_t)node * 32 + q]
                            : make_float4(0.f, 0.f, 0.f, 0.f);
    }
    __syncthreads();

    int nd = tid >> 3;
    int q = tid & 7;
    int node = nodeBase + nd;
    if (node >= n) return;

    const ulonglong2* sWu = (const ulonglong2*)sW4;
    unsigned long long a01 = 0ULL, a23 = 0ULL;
#pragma unroll 8
    for (int k4 = 0; k4 < 32; k4++) {
        float4 xv = sx4[nd * 32 + k4];
        unsigned long long d0 = pack2(xv.x, xv.x);
        unsigned long long d1 = pack2(xv.y, xv.y);
        unsigned long long d2 = pack2(xv.z, xv.z);
        unsigned long long d3 = pack2(xv.w, xv.w);
        ulonglong2 w0 = sWu[(4 * k4 + 0) * 8 + q];
        ulonglong2 w1 = sWu[(4 * k4 + 1) * 8 + q];
        ulonglong2 w2 = sWu[(4 * k4 + 2) * 8 + q];
        ulonglong2 w3 = sWu[(4 * k4 + 3) * 8 + q];
        a01 = fma2(d0, w0.x, a01); a23 = fma2(d0, w0.y, a23);
        a01 = fma2(d1, w1.x, a01); a23 = fma2(d1, w1.y, a23);
        a01 = fma2(d2, w2.x, a01); a23 = fma2(d2, w2.y, a23);
        a01 = fma2(d3, w3.x, a01); a23 = fma2(d3, w3.y, a23);
    }
    float2 lo = unpack2(a01), hi = unpack2(a23);
    float di = g_dinv[node];
    float4 hs = make_float4(lo.x * di, lo.y * di, hi.x * di, hi.y * di);
    ((float4*)g_h)[(size_t)node * 8 + q] = hs;
}

// ---------------- GEMM2: hs2 = (relu(acc)@W2)*di ----------------
__global__ void k_gemm2(const float* __restrict__ W2, int n) {
    __shared__ __align__(16) float4 sW4[HID * 8];
    __shared__ __align__(16) float4 sa4[32 * 8];
    int tid = threadIdx.x;
    int nodeBase = blockIdx.x * 32;

    for (int i = tid; i < HID * 8; i += 256) sW4[i] = ((const float4*)W2)[i];
    {
        int nd = tid >> 3, q = tid & 7;
        int node = nodeBase + nd;
        float4 v = make_float4(0.f, 0.f, 0.f, 0.f);
        if (node < n) {
            v = ((const float4*)g_acc)[(size_t)node * 8 + q];
            v.x = fmaxf(v.x, 0.f); v.y = fmaxf(v.y, 0.f);
            v.z = fmaxf(v.z, 0.f); v.w = fmaxf(v.w, 0.f);
        }
        sa4[nd * 8 + q] = v;
    }
    __syncthreads();

    int nd = tid >> 3;
    int q = tid & 7;
    int node = nodeBase + nd;
    if (node >= n) return;

    const ulonglong2* sWu = (const ulonglong2*)sW4;
    unsigned long long a01 = 0ULL, a23 = 0ULL;
#pragma unroll
    for (int k4 = 0; k4 < 8; k4++) {
        float4 xv = sa4[nd * 8 + k4];
        unsigned long long d0 = pack2(xv.x, xv.x);
        unsigned long long d1 = pack2(xv.y, xv.y);
        unsigned long long d2 = pack2(xv.z, xv.z);
        unsigned long long d3 = pack2(xv.w, xv.w);
        ulonglong2 w0 = sWu[(4 * k4 + 0) * 8 + q];
        ulonglong2 w1 = sWu[(4 * k4 + 1) * 8 + q];
        ulonglong2 w2 = sWu[(4 * k4 + 2) * 8 + q];
        ulonglong2 w3 = sWu[(4 * k4 + 3) * 8 + q];
        a01 = fma2(d0, w0.x, a01); a23 = fma2(d0, w0.y, a23);
        a01 = fma2(d1, w1.x, a01); a23 = fma2(d1, w1.y, a23);
        a01 = fma2(d2, w2.x, a01); a23 = fma2(d2, w2.y, a23);
        a01 = fma2(d3, w3.x, a01); a23 = fma2(d3, w3.y, a23);
    }
    float2 lo = unpack2(a01), hi = unpack2(a23);
    float di = g_dinv[node];
    float4 hs = make_float4(lo.x * di, lo.y * di, hi.x * di, hi.y * di);
    ((float4*)g_h)[(size_t)node * 8 + q] = hs;
}

// ---------------- aggregation (R7-proven): unroll 4, pure-store epilogue ----------
__device__ __forceinline__ void aggregate_node(const float* __restrict__ bias,
                                               float* __restrict__ outrow,
                                               int node, int lane) {
    int j = lane >> 3;  // edge slot 0..3
    int q = lane & 7;   // float4 lane 0..7

    int beg = g_off[node];
    int end = g_off[node + 1];

    const float4* H = (const float4*)g_h;
    float4 acc = make_float4(0.f, 0.f, 0.f, 0.f);
#pragma unroll 4
    for (int i = beg + j; i < end; i += 4) {
        int s = g_csr_src[i];
        float4 v = __ldg(&H[(size_t)s * 8 + q]);
        acc.x += v.x; acc.y += v.y; acc.z += v.z; acc.w += v.w;
    }
#pragma unroll
    for (int m = 8; m <= 16; m <<= 1) {
        acc.x += __shfl_xor_sync(0xFFFFFFFFu, acc.x, m);
        acc.y += __shfl_xor_sync(0xFFFFFFFFu, acc.y, m);
        acc.z += __shfl_xor_sync(0xFFFFFFFFu, acc.z, m);
        acc.w += __shfl_xor_sync(0xFFFFFFFFu, acc.w, m);
    }
    if (j == 0) {
        float dd = g_dinv[node];
        float4 self = __ldg(&H[(size_t)node * 8 + q]);  // self-loop (hs)
        float4 bv = __ldg(((const float4*)bias) + q);
        float4 r;
        r.x = fmaf(dd, acc.x + self.x, bv.x);
        r.y = fmaf(dd, acc.y + self.y, bv.y);
        r.z = fmaf(dd, acc.z + self.z, bv.z);
        r.w = fmaf(dd, acc.w + self.w, bv.w);
        ((float4*)outrow)[q] = r;  // pure store
    }
}

__global__ void k_aggregate1(const float* __restrict__ b1, int n) {
    int warp_id = (blockIdx.x * blockDim.x + threadIdx.x) >> 5;
    if (warp_id >= n) return;
    aggregate_node(b1, g_acc + (size_t)warp_id * HID, warp_id, threadIdx.x & 31);
}

__global__ void k_aggregate2(const float* __restrict__ b2,
                             float* __restrict__ out, int n) {
    int warp_id = (blockIdx.x * blockDim.x + threadIdx.x) >> 5;
    if (warp_id >= n) return;
    aggregate_node(b2, out + (size_t)warp_id * HID, warp_id, threadIdx.x & 31);
}

extern "C" void kernel_launch(void* const* d_in, const int* in_sizes, int n_in,
                              void* d_out, int out_size) {
    const float* x  = (const float*)d_in[0];
    const int*   ei = (const int*)d_in[1];
    const float* W1 = (const float*)d_in[2];
    const float* b1 = (const float*)d_in[3];
    const float* W2 = (const float*)d_in[4];
    const float* b2 = (const float*)d_in[5];
    float* out = (float*)d_out;

    const int N = in_sizes[0] / IN_CH;
    const int E = in_sizes[1] / 2;
    const int nb = (N + SCAN_B - 1) / SCAN_B;

    k_detect_zero<<<(N + 255) / 256, 256>>>(ei, E, N);
    k_deg<<<(E + 255) / 256, 256>>>(ei, E);

    k_partial<<<nb, SCAN_B>>>(N);
    k_scanpart<<<1, MAX_PART>>>(nb, N, E);
    k_local<<<nb, SCAN_B>>>(N);

    k_fill<<<(E + 255) / 256, 256>>>(ei, E);

    k_gemm1<<<(N + 31) / 32, 256>>>(x, W1, N);
    {
        long long thr = (long long)N * 32;
        k_aggregate1<<<(int)((thr + 255) / 256), 256>>>(b1, N);
    }

    k_gemm2<<<(N + 31) / 32, 256>>>(W2, N);
    {
        long long thr = (long long)N * 32;
        k_aggregate2<<<(int)((thr + 255) / 256), 256>>>(b2, out, N);
    }
}